// round 10
// baseline (speedup 1.0000x reference)
#include <cuda_runtime.h>

// StackMemory_9122510536894
//
// Degenerate scan: stack row 1 is read as s1 but NEVER written, so s1 == 0
// for every step. new_top[t] = softmax(W*h_t + b)[0] * sigmoid(D*h_t),
// broadcast over H=400; stack rows 1..31 are zero in every output slab.
// No recurrence -> embarrassingly parallel over t. HBM-write-bound:
// 419.4 MB stores + 13.1 MB loads; roofline ~60-75 us. STG.128 issue rate
// (~42.7 B/cyc/SM * 148 SM) meets the ~6300 B/cyc LTS cap exactly, so
// 128-bit stores are mandatory and sufficient.

#define HDIM    400
#define SDEPTH  32
#define TSTEPS  8192
#define NTHREADS 256

__global__ __launch_bounds__(NTHREADS) void StackMemory_kernel(
    const float* __restrict__ hs,   // [T, H]
    const float* __restrict__ W,    // [3, H]
    const float* __restrict__ bv,   // [3]
    const float* __restrict__ Dv,   // [H]
    float* __restrict__ out)        // [T, 32, H]
{
    const int t   = blockIdx.x;
    const int tid = threadIdx.x;
    const float* __restrict__ h = hs + (size_t)t * HDIM;

    // ---- Phase 1: four fused dot products over H=400 ----
    float s0 = 0.f, s1 = 0.f, s2 = 0.f, s3 = 0.f;
    for (int i = tid; i < HDIM; i += NTHREADS) {
        float x = h[i];
        s0 = fmaf(x, __ldg(&W[i]),          s0);
        s1 = fmaf(x, __ldg(&W[HDIM + i]),   s1);
        s2 = fmaf(x, __ldg(&W[2*HDIM + i]), s2);
        s3 = fmaf(x, __ldg(&Dv[i]),         s3);
    }
    #pragma unroll
    for (int off = 16; off > 0; off >>= 1) {
        s0 += __shfl_down_sync(0xffffffffu, s0, off);
        s1 += __shfl_down_sync(0xffffffffu, s1, off);
        s2 += __shfl_down_sync(0xffffffffu, s2, off);
        s3 += __shfl_down_sync(0xffffffffu, s3, off);
    }
    __shared__ float red[NTHREADS / 32][4];
    __shared__ float c_sh;
    const int wid  = tid >> 5;
    const int lane = tid & 31;
    if (lane == 0) {
        red[wid][0] = s0; red[wid][1] = s1; red[wid][2] = s2; red[wid][3] = s3;
    }
    __syncthreads();
    if (tid == 0) {
        float a0 = bv[0], a1 = bv[1], a2 = bv[2], dv = 0.f;
        #pragma unroll
        for (int w = 0; w < NTHREADS / 32; ++w) {
            a0 += red[w][0]; a1 += red[w][1]; a2 += red[w][2]; dv += red[w][3];
        }
        // stable softmax over 3 logits, component 0
        float m  = fmaxf(a0, fmaxf(a1, a2));
        float e0 = expf(a0 - m), e1 = expf(a1 - m), e2 = expf(a2 - m);
        float pu = e0 / (e0 + e1 + e2);
        float sg = 1.0f / (1.0f + expf(-dv));
        c_sh = pu * sg;
    }
    __syncthreads();
    const float c = c_sh;

    // ---- Phase 2: write the contiguous 32x400 slab for this t (51.2 KB) ----
    // First 100 float4s = c, remaining 3100 = 0.
    float4* __restrict__ o = (float4*)(out + (size_t)t * (SDEPTH * HDIM));
    const float4 cv = make_float4(c, c, c, c);
    const float4 zv = make_float4(0.f, 0.f, 0.f, 0.f);
    const int nvec  = (SDEPTH * HDIM) / 4;   // 3200
    const int ncvec = HDIM / 4;              // 100

    // Peeled first stride: c-region (tid<100) + zero patch up to 256.
    o[tid] = (tid < ncvec) ? cv : zv;

    // Branch-free zero stream, 2x unrolled for store MLP.
    int i = tid + NTHREADS;
    for (; i + NTHREADS < nvec; i += 2 * NTHREADS) {
        o[i]            = zv;
        o[i + NTHREADS] = zv;
    }
    if (i < nvec) o[i] = zv;
}

extern "C" void kernel_launch(void* const* d_in, const int* in_sizes, int n_in,
                              void* d_out, int out_size) {
    const float* hs = (const float*)d_in[0];  // hidden_state [1, 8192, 400]
    const float* W  = (const float*)d_in[1];  // W_ap [3, 400]
    const float* bv = (const float*)d_in[2];  // b_ap [3]
    const float* Dv = (const float*)d_in[3];  // D [1, 400]
    float* out = (float*)d_out;               // [1, 8192, 32, 400]

    StackMemory_kernel<<<TSTEPS, NTHREADS>>>(hs, W, bv, Dv, out);
}

// round 11
// speedup vs baseline: 1.0364x; 1.0364x over previous
#include <cuda_runtime.h>

// StackMemory_9122510536894 — R10: split compute/store kernels.
//
// Degenerate scan (proven): stack row 1 is never written => s1 == 0 =>
// out[0,t,0,:] = softmax(W*h_t+b)[0] * sigmoid(D*h_t), rows 1..31 == 0.
//
// R10 baseline (single fused kernel): 70.1us, DRAM=68.9%, occ=67.9%.
// Theory: reduction phase + barriers dilute store issue. Split:
//   K1 compute_c: warp-per-t, shuffle-only reduction -> g_c[8192]  (~4us)
//   K2 write_out: pure STG.128 stream, no smem/barriers, __stcs     (~58us)
// Predicted: 58-64us total, DRAM 80-88% on K2.

#define HDIM    400
#define SDEPTH  32
#define TSTEPS  8192

__device__ float g_c[TSTEPS];   // per-t scalar, K1 -> K2

// ---------------- K1: compute c_t, one warp per t ----------------
__global__ __launch_bounds__(256) void compute_c_kernel(
    const float* __restrict__ hs,   // [T, H]
    const float* __restrict__ W,    // [3, H]
    const float* __restrict__ bv,   // [3]
    const float* __restrict__ Dv)   // [H]
{
    const int gwarp = (blockIdx.x * blockDim.x + threadIdx.x) >> 5;
    const int lane  = threadIdx.x & 31;
    if (gwarp >= TSTEPS) return;

    const float* __restrict__ h = hs + (size_t)gwarp * HDIM;

    float s0 = 0.f, s1 = 0.f, s2 = 0.f, s3 = 0.f;
    for (int i = lane; i < HDIM; i += 32) {
        float x = h[i];
        s0 = fmaf(x, __ldg(&W[i]),          s0);
        s1 = fmaf(x, __ldg(&W[HDIM + i]),   s1);
        s2 = fmaf(x, __ldg(&W[2*HDIM + i]), s2);
        s3 = fmaf(x, __ldg(&Dv[i]),         s3);
    }
    #pragma unroll
    for (int off = 16; off > 0; off >>= 1) {
        s0 += __shfl_down_sync(0xffffffffu, s0, off);
        s1 += __shfl_down_sync(0xffffffffu, s1, off);
        s2 += __shfl_down_sync(0xffffffffu, s2, off);
        s3 += __shfl_down_sync(0xffffffffu, s3, off);
    }
    if (lane == 0) {
        float a0 = s0 + bv[0], a1 = s1 + bv[1], a2 = s2 + bv[2];
        // stable softmax over 3 logits, component 0
        float m  = fmaxf(a0, fmaxf(a1, a2));
        float e0 = expf(a0 - m), e1 = expf(a1 - m), e2 = expf(a2 - m);
        float pu = e0 / (e0 + e1 + e2);
        float sg = 1.0f / (1.0f + expf(-s3));
        g_c[gwarp] = pu * sg;
    }
}

// ---------------- K2: pure store stream, block per t ----------------
#define NTHREADS 256

__global__ __launch_bounds__(NTHREADS) void write_out_kernel(
    float* __restrict__ out)        // [T, 32, H]
{
    const int t   = blockIdx.x;
    const int tid = threadIdx.x;

    const float  c  = __ldg(&g_c[t]);
    float4* __restrict__ o = (float4*)(out + (size_t)t * (SDEPTH * HDIM));
    const float4 cv = make_float4(c, c, c, c);
    const float4 zv = make_float4(0.f, 0.f, 0.f, 0.f);
    const int nvec  = (SDEPTH * HDIM) / 4;   // 3200
    const int ncvec = HDIM / 4;              // 100

    // Peeled first stride: c-region (tid<100) + zero patch up to 256.
    __stcs(&o[tid], (tid < ncvec) ? cv : zv);

    // Branch-free streaming zero wall, 4x unrolled.
    int i = tid + NTHREADS;
    for (; i + 3 * NTHREADS < nvec; i += 4 * NTHREADS) {
        __stcs(&o[i],                zv);
        __stcs(&o[i +     NTHREADS], zv);
        __stcs(&o[i + 2 * NTHREADS], zv);
        __stcs(&o[i + 3 * NTHREADS], zv);
    }
    for (; i < nvec; i += NTHREADS) {
        __stcs(&o[i], zv);
    }
}

extern "C" void kernel_launch(void* const* d_in, const int* in_sizes, int n_in,
                              void* d_out, int out_size) {
    const float* hs = (const float*)d_in[0];  // hidden_state [1, 8192, 400]
    const float* W  = (const float*)d_in[1];  // W_ap [3, 400]
    const float* bv = (const float*)d_in[2];  // b_ap [3]
    const float* Dv = (const float*)d_in[3];  // D [1, 400]
    float* out = (float*)d_out;               // [1, 8192, 32, 400]

    // K1: 8192 warps = 8192*32 threads / 256 = 1024 blocks
    compute_c_kernel<<<(TSTEPS * 32) / 256, 256>>>(hs, W, bv, Dv);
    // K2: block per t
    write_out_kernel<<<TSTEPS, NTHREADS>>>(out);
}

// round 12
// speedup vs baseline: 1.1400x; 1.0999x over previous
#include <cuda_runtime.h>

// StackMemory_9122510536894 — R12: barrier-free asymmetric fusion.
//
// Degenerate scan (proven): stack row 1 never written => s1 == 0 =>
// out[0,t,0,:] = softmax(W*h_t+b)[0] * sigmoid(D*h_t), rows 1..31 == 0.
//
// R11: split kernels = 67.6us (K2 store = 58.0us @ 78.6% DRAM, K1+overhead
// ~9.7us serial prologue). The zero rows (31/32 of all bytes) don't depend
// on c, so fuse with NO barrier: warp 0 computes c in-warp and writes the
// c-region; warps 1..7 stream zeros from cycle 0. Reduction hides under
// the store wall. Predicted 59-62us.

#define HDIM    400
#define SDEPTH  32
#define TSTEPS  8192
#define NTHREADS 256

__global__ __launch_bounds__(NTHREADS) void StackMemory_kernel(
    const float* __restrict__ hs,   // [T, H]
    const float* __restrict__ W,    // [3, H]
    const float* __restrict__ bv,   // [3]
    const float* __restrict__ Dv,   // [H]
    float* __restrict__ out)        // [T, 32, H]
{
    const int t   = blockIdx.x;
    const int tid = threadIdx.x;

    float4* __restrict__ o = (float4*)(out + (size_t)t * (SDEPTH * HDIM));
    const float4 zv = make_float4(0.f, 0.f, 0.f, 0.f);
    const int nvec  = (SDEPTH * HDIM) / 4;   // 3200
    const int ncvec = HDIM / 4;              // 100

    if (tid >= 32) {
        // ---- Warps 1..7: zero wall, starts immediately, no dependency ----
        // float4 indices [100, 3200), 224 threads -> idx = tid + 68 stride 224.
        int i = tid + (ncvec - 32);           // tid-32+100
        for (; i + 3 * (NTHREADS - 32) < nvec; i += 4 * (NTHREADS - 32)) {
            __stcs(&o[i],                      zv);
            __stcs(&o[i +     (NTHREADS - 32)], zv);
            __stcs(&o[i + 2 * (NTHREADS - 32)], zv);
            __stcs(&o[i + 3 * (NTHREADS - 32)], zv);
        }
        for (; i < nvec; i += (NTHREADS - 32)) {
            __stcs(&o[i], zv);
        }
        return;
    }

    // ---- Warp 0: compute c_t in-warp (float4 loads, shuffle reduce) ----
    const int lane = tid;  // 0..31
    const float4* __restrict__ h4 = (const float4*)(hs + (size_t)t * HDIM);
    const float4* __restrict__ W0 = (const float4*)(W);
    const float4* __restrict__ W1 = (const float4*)(W + HDIM);
    const float4* __restrict__ W2 = (const float4*)(W + 2 * HDIM);
    const float4* __restrict__ D4 = (const float4*)(Dv);

    float s0 = 0.f, s1 = 0.f, s2 = 0.f, s3 = 0.f;
    for (int j = lane; j < ncvec; j += 32) {   // 100 float4s: 3-4 per lane
        float4 x  = h4[j];
        float4 w0 = __ldg(&W0[j]);
        float4 w1 = __ldg(&W1[j]);
        float4 w2 = __ldg(&W2[j]);
        float4 d  = __ldg(&D4[j]);
        s0 = fmaf(x.x, w0.x, fmaf(x.y, w0.y, fmaf(x.z, w0.z, fmaf(x.w, w0.w, s0))));
        s1 = fmaf(x.x, w1.x, fmaf(x.y, w1.y, fmaf(x.z, w1.z, fmaf(x.w, w1.w, s1))));
        s2 = fmaf(x.x, w2.x, fmaf(x.y, w2.y, fmaf(x.z, w2.z, fmaf(x.w, w2.w, s2))));
        s3 = fmaf(x.x, d.x,  fmaf(x.y, d.y,  fmaf(x.z, d.z,  fmaf(x.w, d.w,  s3))));
    }
    #pragma unroll
    for (int off = 16; off > 0; off >>= 1) {
        s0 += __shfl_down_sync(0xffffffffu, s0, off);
        s1 += __shfl_down_sync(0xffffffffu, s1, off);
        s2 += __shfl_down_sync(0xffffffffu, s2, off);
        s3 += __shfl_down_sync(0xffffffffu, s3, off);
    }
    float c;
    if (lane == 0) {
        float a0 = s0 + bv[0], a1 = s1 + bv[1], a2 = s2 + bv[2];
        // stable softmax over 3 logits, component 0
        float m  = fmaxf(a0, fmaxf(a1, a2));
        float e0 = expf(a0 - m), e1 = expf(a1 - m), e2 = expf(a2 - m);
        float pu = e0 / (e0 + e1 + e2);
        float sg = 1.0f / (1.0f + expf(-s3));
        c = pu * sg;
    }
    c = __shfl_sync(0xffffffffu, c, 0);

    // Warp 0 writes the 100-float4 c-region (3-4 per lane).
    const float4 cv = make_float4(c, c, c, c);
    for (int j = lane; j < ncvec; j += 32) {
        __stcs(&o[j], cv);
    }
}

extern "C" void kernel_launch(void* const* d_in, const int* in_sizes, int n_in,
                              void* d_out, int out_size) {
    const float* hs = (const float*)d_in[0];  // hidden_state [1, 8192, 400]
    const float* W  = (const float*)d_in[1];  // W_ap [3, 400]
    const float* bv = (const float*)d_in[2];  // b_ap [3]
    const float* Dv = (const float*)d_in[3];  // D [1, 400]
    float* out = (float*)d_out;               // [1, 8192, 32, 400]

    StackMemory_kernel<<<TSTEPS, NTHREADS>>>(hs, W, bv, Dv, out);
}